// round 3
// baseline (speedup 1.0000x reference)
#include <cuda_runtime.h>
#include <cstdint>

#define BB 512
#define TT 2000
#define HH 50
#define CH 32          // steps per chunk
#define HSTRIDE 68     // floats per hist row (16B aligned rows)

typedef unsigned long long ull;

__device__ __forceinline__ ull packf2(float a, float b) {
    ull r;
    asm("mov.b64 %0, {%1, %2};" : "=l"(r) : "f"(a), "f"(b));
    return r;
}
__device__ __forceinline__ void unpackf2(ull v, float& lo, float& hi) {
    asm("mov.b64 {%0, %1}, %2;" : "=f"(lo), "=f"(hi) : "l"(v));
}
#define FMA2(acc, a, b) \
    asm("fma.rn.f32x2 %0, %1, %2, %0;" : "+l"(acc) : "l"(a), "l"(b))
#define ADD2(dst, a, b) \
    asm("add.rn.f32x2 %0, %1, %2;" : "=l"(dst) : "l"(a), "l"(b))

__global__ __launch_bounds__(128, 1)
void rnn_kernel(const float* __restrict__ x,
                const float* __restrict__ W_ih,
                const float* __restrict__ W_hh,
                const float* __restrict__ b_ih,
                const float* __restrict__ b_hh,
                const float* __restrict__ W_out,
                const float* __restrict__ b_out,
                float* __restrict__ y)
{
    // linear 33-row history per warp: step s reads row s, writes row s+1
    __shared__ __align__(16) float hist[4][CH + 1][HSTRIDE];   // 35,904 B
    __shared__ __align__(16) float xs[4][2][CH][4];            // staged x, 4,096 B
    __shared__ ull  wosh[3][25];
    __shared__ float bosh[3];

    const int warp = threadIdx.x >> 5;
    const int lane = threadIdx.x & 31;
    const int tid  = threadIdx.x;
    const int b = blockIdx.x * 4 + warp;

    // packed W_out pairs (block-common)
    if (tid < 75) {
        const int d = tid / 25, q = tid % 25;
        wosh[d][q] = packf2(W_out[d * HH + 2 * q], W_out[d * HH + 2 * q + 1]);
    }
    if (tid < 3) bosh[tid] = b_out[tid];

    float* const hwarp = &hist[warp][0][0];
    // h_{-1} = 0 in row 0
    hwarp[lane] = 0.f;
    hwarp[lane + 32] = 0.f;

    const int j0 = lane;
    const int j1 = lane + 32;
    const bool j1v = (j1 < HH);

    // W_hh packed: w0[q] = (W_hh[j0][2q], W_hh[j0][2q+1]), q = 0..24
    ull w0[25], w1[25];
#pragma unroll
    for (int q = 0; q < 25; q++) {
        w0[q] = packf2(W_hh[j0 * HH + 2 * q], W_hh[j0 * HH + 2 * q + 1]);
        w1[q] = j1v ? packf2(W_hh[j1 * HH + 2 * q], W_hh[j1 * HH + 2 * q + 1]) : 0ull;
    }
    const float wi0a = W_ih[j0 * 3 + 0], wi0b = W_ih[j0 * 3 + 1], wi0c = W_ih[j0 * 3 + 2];
    const float bias0 = b_ih[j0] + b_hh[j0];
    const float wi1a = j1v ? W_ih[j1 * 3 + 0] : 0.f;
    const float wi1b = j1v ? W_ih[j1 * 3 + 1] : 0.f;
    const float wi1c = j1v ? W_ih[j1 * 3 + 2] : 0.f;
    const float bias1 = j1v ? (b_ih[j1] + b_hh[j1]) : 0.f;

    const float* __restrict__ xb = x + (size_t)b * TT * 3;
    float* __restrict__ yb = y + (size_t)b * TT * 3;

    // ---- stage x chunk 0 into xs[warp][0] ----
    {
        const int g = lane * 4;
        if (g < 3 * CH) {
            const float4 v = *reinterpret_cast<const float4*>(xb + g);
            const float c[4] = {v.x, v.y, v.z, v.w};
#pragma unroll
            for (int i = 0; i < 4; i++) {
                const int gi = g + i;
                xs[warp][0][gi / 3][gi % 3] = c[i];
            }
        }
    }
    __syncthreads();   // wosh/bosh visibility across warps

    int xbuf = 0;
    for (int base = 0; base < TT; base += CH) {
        const int cnt = min(CH, TT - base);

        // kick prefetch of next chunk's x (latency hidden behind 32 steps)
        float4 pf;
        const int ncnt = min(CH, TT - base - CH);
        const bool dopf = (base + CH < TT) && (lane * 4 < 3 * ncnt);
        if (dopf) pf = *reinterpret_cast<const float4*>(xb + 3 * (base + CH) + lane * 4);

        // ---- cnt steps, unrolled by 8 ----
        for (int gg = 0; gg * 8 < cnt; gg++) {
#pragma unroll
            for (int u = 0; u < 8; u++) {
                const int s = gg * 8 + u;
                const float4 xv = *reinterpret_cast<const float4*>(&xs[warp][xbuf][s][0]);
                const float xh0 = fmaf(xv.z, wi0c, fmaf(xv.y, wi0b, fmaf(xv.x, wi0a, bias0)));
                const float xh1 = fmaf(xv.z, wi1c, fmaf(xv.y, wi1b, fmaf(xv.x, wi1a, bias1)));

                const float* hr = hwarp + s * HSTRIDE;
                ull a0[4] = {0ull, 0ull, 0ull, 0ull};
                ull a1[4] = {0ull, 0ull, 0ull, 0ull};
#pragma unroll
                for (int p = 0; p < 12; p++) {
                    const ulonglong2 hv = *reinterpret_cast<const ulonglong2*>(hr + 4 * p);
                    FMA2(a0[(2 * p) & 3], hv.x, w0[2 * p]);
                    FMA2(a0[(2 * p + 1) & 3], hv.y, w0[2 * p + 1]);
                    FMA2(a1[(2 * p) & 3], hv.x, w1[2 * p]);
                    FMA2(a1[(2 * p + 1) & 3], hv.y, w1[2 * p + 1]);
                }
                const ull hl = *reinterpret_cast<const ull*>(hr + 48);
                FMA2(a0[0], hl, w0[24]);
                FMA2(a1[0], hl, w1[24]);

                ull t0, t1, s0, s1;
                ADD2(t0, a0[0], a0[1]); ADD2(t1, a0[2], a0[3]); ADD2(s0, t0, t1);
                ADD2(t0, a1[0], a1[1]); ADD2(t1, a1[2], a1[3]); ADD2(s1, t0, t1);
                float l0, u0, l1, u1;
                unpackf2(s0, l0, u0);
                unpackf2(s1, l1, u1);
                const float h0 = fmaxf(xh0 + (l0 + u0), 0.f);
                const float h1 = fmaxf(xh1 + (l1 + u1), 0.f);

                float* hw = hwarp + (s + 1) * HSTRIDE;
                hw[lane] = h0;
                if (j1v) hw[lane + 32] = h1;
            }
        }

        // carry: row cnt -> row 0 for next chunk
        {
            const float c0 = hwarp[cnt * HSTRIDE + lane];
            hwarp[lane] = c0;
            if (j1v) {
                const float c1 = hwarp[cnt * HSTRIDE + lane + 32];
                hwarp[lane + 32] = c1;
            }
        }

        // store prefetched x into the other buffer
        if (dopf) {
            const int g = lane * 4;
            const float c[4] = {pf.x, pf.y, pf.z, pf.w};
#pragma unroll
            for (int i = 0; i < 4; i++) {
                const int gi = g + i;
                xs[warp][xbuf ^ 1][gi / 3][gi % 3] = c[i];
            }
        }

        // ---- chunk projection: lane s owns timestep base+s (reads row s+1) ----
        if (lane < cnt) {
            const float* pr = hwarp + (lane + 1) * HSTRIDE;
            ull a0 = 0ull, c0 = 0ull, a1 = 0ull, c1 = 0ull, a2 = 0ull, c2 = 0ull;
#pragma unroll
            for (int p = 0; p < 12; p++) {
                const ulonglong2 hv = *reinterpret_cast<const ulonglong2*>(pr + 4 * p);
                FMA2(a0, hv.x, wosh[0][2 * p]); FMA2(c0, hv.y, wosh[0][2 * p + 1]);
                FMA2(a1, hv.x, wosh[1][2 * p]); FMA2(c1, hv.y, wosh[1][2 * p + 1]);
                FMA2(a2, hv.x, wosh[2][2 * p]); FMA2(c2, hv.y, wosh[2][2 * p + 1]);
            }
            const ull hl = *reinterpret_cast<const ull*>(pr + 48);
            FMA2(a0, hl, wosh[0][24]);
            FMA2(a1, hl, wosh[1][24]);
            FMA2(a2, hl, wosh[2][24]);

            ull s0, s1, s2;
            ADD2(s0, a0, c0); ADD2(s1, a1, c1); ADD2(s2, a2, c2);
            float p0l, p0h, p1l, p1h, p2l, p2h;
            unpackf2(s0, p0l, p0h);
            unpackf2(s1, p1l, p1h);
            unpackf2(s2, p2l, p2h);
            float* yo = yb + (size_t)(base + lane) * 3;
            yo[0] = p0l + p0h + bosh[0];
            yo[1] = p1l + p1h + bosh[1];
            yo[2] = p2l + p2h + bosh[2];
        }

        xbuf ^= 1;
    }
}

extern "C" void kernel_launch(void* const* d_in, const int* in_sizes, int n_in,
                              void* d_out, int out_size) {
    const float* x     = (const float*)d_in[0];
    const float* W_ih  = (const float*)d_in[1];
    const float* W_hh  = (const float*)d_in[2];
    const float* b_ih  = (const float*)d_in[3];
    const float* b_hh  = (const float*)d_in[4];
    const float* W_out = (const float*)d_in[5];
    const float* b_out = (const float*)d_in[6];
    float* y = (float*)d_out;

    rnn_kernel<<<BB / 4, 128>>>(x, W_ih, W_hh, b_ih, b_hh, W_out, b_out, y);
}

// round 4
// speedup vs baseline: 1.4426x; 1.4426x over previous
#include <cuda_runtime.h>
#include <cstdint>

#define BB 512
#define TT 2000
#define HH 50
#define CH 32
#define HSTRIDE 68
#define NB 4            // batch elements (warp pairs) per CTA

typedef unsigned long long ull;

__device__ __forceinline__ ull packf2(float a, float b) {
    ull r;
    asm("mov.b64 %0, {%1, %2};" : "=l"(r) : "f"(a), "f"(b));
    return r;
}
__device__ __forceinline__ void unpackf2(ull v, float& lo, float& hi) {
    asm("mov.b64 {%0, %1}, %2;" : "=f"(lo), "=f"(hi) : "l"(v));
}
#define FMA2(acc, a, b) \
    asm("fma.rn.f32x2 %0, %1, %2, %0;" : "+l"(acc) : "l"(a), "l"(b))
#define ADD2(dst, a, b) \
    asm("add.rn.f32x2 %0, %1, %2;" : "=l"(dst) : "l"(a), "l"(b))
#define PAIR_BAR(id) \
    asm volatile("bar.sync %0, 64;" :: "r"(id) : "memory")

__global__ __launch_bounds__(256, 1)
void rnn_kernel(const float* __restrict__ x,
                const float* __restrict__ W_ih,
                const float* __restrict__ W_hh,
                const float* __restrict__ b_ih,
                const float* __restrict__ b_hh,
                const float* __restrict__ W_out,
                const float* __restrict__ b_out,
                float* __restrict__ y)
{
    // per-pair 33-row history: step s reads row s, writes row s+1
    __shared__ __align__(16) float hist[NB][CH + 1][HSTRIDE];  // 35,904 B
    __shared__ __align__(16) float xsh[NB][2][CH][4];          //  4,096 B
    __shared__ ull  wosh[3][25];
    __shared__ float bosh[3];

    const int tid  = threadIdx.x;
    const int warp = tid >> 5;
    const int lane = tid & 31;
    const int pair = warp >> 1;       // 0..3  -> batch within CTA
    const int half = warp & 1;        // which 25 j's this warp owns
    const int pairtid = half * 32 + lane;   // 0..63 within the pair
    const int barid = pair + 1;
    const int b = blockIdx.x * NB + pair;

    // ---- block-common packed W_out ----
    if (tid < 75) {
        const int d = tid / 25, q = tid % 25;
        wosh[d][q] = packf2(W_out[d * HH + 2 * q], W_out[d * HH + 2 * q + 1]);
    }
    if (tid < 3) bosh[tid] = b_out[tid];

    const int j = half * 25 + lane;         // this lane's output index
    const bool active = (lane < 25);

    // ---- per-lane weights: 25 packed k-pairs of W_hh row j ----
    ull w[25];
#pragma unroll
    for (int q = 0; q < 25; q++)
        w[q] = active ? packf2(W_hh[j * HH + 2 * q], W_hh[j * HH + 2 * q + 1]) : 0ull;
    const float wia = active ? W_ih[j * 3 + 0] : 0.f;
    const float wib = active ? W_ih[j * 3 + 1] : 0.f;
    const float wic = active ? W_ih[j * 3 + 2] : 0.f;
    const float bias = active ? (b_ih[j] + b_hh[j]) : 0.f;

    float* const hwarp = &hist[pair][0][0];
    if (active) hwarp[j] = 0.f;             // h_{-1} = 0, both halves cover 0..49

    const float* __restrict__ xb = x + (size_t)b * TT * 3;
    float* __restrict__ yb = y + (size_t)b * TT * 3;

    // ---- stage x chunk 0 (96 floats via 24 float4 loads across the pair) ----
    if (pairtid < 24) {
        const float4 v = *reinterpret_cast<const float4*>(xb + pairtid * 4);
        const float c[4] = {v.x, v.y, v.z, v.w};
#pragma unroll
        for (int i = 0; i < 4; i++) {
            const int gi = pairtid * 4 + i;
            xsh[pair][0][gi / 3][gi % 3] = c[i];
        }
    }
    __syncthreads();

    int xbuf = 0;
    for (int base = 0; base < TT; base += CH) {
        const int cnt = min(CH, TT - base);

        // prefetch next chunk's x into regs (consumed after the step loop)
        float4 pf;
        const bool dopf = (base + CH < TT) && (pairtid < 24);
        if (dopf) pf = *reinterpret_cast<const float4*>(xb + 3 * (base + CH) + pairtid * 4);

        // ---- recurrence steps ----
        const float* hr = hwarp;             // row s
        float* hw = hwarp + HSTRIDE;         // row s+1
#pragma unroll 4
        for (int s = 0; s < cnt; s++) {
            const float4 xv = *reinterpret_cast<const float4*>(&xsh[pair][xbuf][s][0]);
            const float xh = fmaf(xv.z, wic, fmaf(xv.y, wib, fmaf(xv.x, wia, bias)));

            ull a0 = 0ull, a1 = 0ull, a2 = 0ull, a3 = 0ull;
#pragma unroll
            for (int p = 0; p < 12; p++) {
                const ulonglong2 hv = *reinterpret_cast<const ulonglong2*>(hr + 4 * p);
                if (p & 1) { FMA2(a2, hv.x, w[2 * p]); FMA2(a3, hv.y, w[2 * p + 1]); }
                else       { FMA2(a0, hv.x, w[2 * p]); FMA2(a1, hv.y, w[2 * p + 1]); }
            }
            const ull hl = *reinterpret_cast<const ull*>(hr + 48);
            FMA2(a0, hl, w[24]);

            ull t0, t1, ss;
            ADD2(t0, a0, a1); ADD2(t1, a2, a3); ADD2(ss, t0, t1);
            float lo, hi;
            unpackf2(ss, lo, hi);
            const float h = fmaxf(xh + (lo + hi), 0.f);

            if (active) hw[j] = h;
            PAIR_BAR(barid);                 // h_t fully visible to both warps
            hr += HSTRIDE;
            hw += HSTRIDE;
        }

        // stage prefetched x into the other buffer
        if (dopf) {
            const float c[4] = {pf.x, pf.y, pf.z, pf.w};
#pragma unroll
            for (int i = 0; i < 4; i++) {
                const int gi = pairtid * 4 + i;
                xsh[pair][xbuf ^ 1][gi / 3][gi % 3] = c[i];
            }
        }
        // carry h_{base+cnt-1} (row cnt) into row 0 for the next chunk
        if (active) hwarp[j] = hwarp[cnt * HSTRIDE + j];
        PAIR_BAR(barid);                     // carry + x staging visible

        // ---- chunk projection over the pair's 64 threads ----
        // warp half 0: thread lane -> y[base+lane][0..1]; half 1: y[base+lane][2]
        if (lane < cnt) {
            const float* pr = hwarp + (lane + 1) * HSTRIDE;
            float* yo = yb + (size_t)(base + lane) * 3;
            if (half == 0) {
                ull a0 = 0ull, c0 = 0ull, a1 = 0ull, c1 = 0ull;
#pragma unroll
                for (int p = 0; p < 12; p++) {
                    const ulonglong2 hv = *reinterpret_cast<const ulonglong2*>(pr + 4 * p);
                    FMA2(a0, hv.x, wosh[0][2 * p]); FMA2(c0, hv.y, wosh[0][2 * p + 1]);
                    FMA2(a1, hv.x, wosh[1][2 * p]); FMA2(c1, hv.y, wosh[1][2 * p + 1]);
                }
                const ull hl = *reinterpret_cast<const ull*>(pr + 48);
                FMA2(a0, hl, wosh[0][24]);
                FMA2(a1, hl, wosh[1][24]);
                ull s0, s1;
                ADD2(s0, a0, c0); ADD2(s1, a1, c1);
                float p0l, p0h, p1l, p1h;
                unpackf2(s0, p0l, p0h);
                unpackf2(s1, p1l, p1h);
                yo[0] = p0l + p0h + bosh[0];
                yo[1] = p1l + p1h + bosh[1];
            } else {
                ull a2 = 0ull, c2 = 0ull;
#pragma unroll
                for (int p = 0; p < 12; p++) {
                    const ulonglong2 hv = *reinterpret_cast<const ulonglong2*>(pr + 4 * p);
                    FMA2(a2, hv.x, wosh[2][2 * p]); FMA2(c2, hv.y, wosh[2][2 * p + 1]);
                }
                const ull hl = *reinterpret_cast<const ull*>(pr + 48);
                FMA2(a2, hl, wosh[2][24]);
                ull s2;
                ADD2(s2, a2, c2);
                float p2l, p2h;
                unpackf2(s2, p2l, p2h);
                yo[2] = p2l + p2h + bosh[2];
            }
        }
        PAIR_BAR(barid);                     // projection reads done before next chunk writes
        xbuf ^= 1;
    }
}

extern "C" void kernel_launch(void* const* d_in, const int* in_sizes, int n_in,
                              void* d_out, int out_size) {
    const float* x     = (const float*)d_in[0];
    const float* W_ih  = (const float*)d_in[1];
    const float* W_hh  = (const float*)d_in[2];
    const float* b_ih  = (const float*)d_in[3];
    const float* b_hh  = (const float*)d_in[4];
    const float* W_out = (const float*)d_in[5];
    const float* b_out = (const float*)d_in[6];
    float* y = (float*)d_out;

    rnn_kernel<<<BB / NB, 256>>>(x, W_ih, W_hh, b_ih, b_hh, W_out, b_out, y);
}